// round 14
// baseline (speedup 1.0000x reference)
#include <cuda_runtime.h>
#include <cuda_bf16.h>
#include <math.h>

#define BB 16
#define TT 1024
#define VV 4096
#define PP 100
#define LL 128
#define NEDIT 64          // 4 blocks per b, 32 paths per block (4 lanes/path)

// scratch (allocation-free rule: __device__ globals)
__device__ unsigned g_map[BB * VV];                       // per-b vocab -> minpos
__device__ unsigned char g_ctok[BB * PP * TT + 128];      // compacted token ids (u8)
__device__ int g_clen[BB * PP];
__device__ float g_scores[BB * PP];
__device__ float g_wers[BB * PP];
__device__ unsigned g_done;

// forced 3-input LOP3 with explicit immLut
#define LOP3_(r, a, b, c, imm)                                          \
    asm("lop3.b32 %0, %1, %2, %3, %4;"                                  \
        : "=r"(r) : "r"(a), "r"(b), "r"(c), "n"(imm))

// ---------------------------------------------------------------------------
// Kernel A1: wide clear of the vocab map (+ done counter).
// ---------------------------------------------------------------------------
__global__ void __launch_bounds__(128) clear_kernel()
{
    const unsigned idx = blockIdx.x * 128u + threadIdx.x;
    uint4* mp = (uint4*)g_map;
    const uint4 f = make_uint4(~0u, ~0u, ~0u, ~0u);
    for (unsigned i = idx; i < (BB * VV) / 4; i += gridDim.x * 128u) mp[i] = f;
    if (idx == 0) g_done = 0;
}

// ---------------------------------------------------------------------------
// Kernel A2: map[b][c] = min label position of char c. id(c) = map[c]+1
// (wraps to 0 for chars not in the label).
// ---------------------------------------------------------------------------
__global__ void __launch_bounds__(128) scatter_kernel(
    const int* __restrict__ labels,
    const int* __restrict__ llen)
{
    const int b = blockIdx.x, tid = threadIdx.x;
    if (tid < llen[b])
        atomicMin(&g_map[(size_t)b * VV + labels[b * LL + tid]], (unsigned)tid);
}

// ---------------------------------------------------------------------------
// Kernel B: CTC-collapse + remap to u8 ids. One block per (b,p).
// valid = tok!=0 && tok!=raw_prev && t<len.
// ---------------------------------------------------------------------------
__global__ void __launch_bounds__(128) compact_kernel(
    const int* __restrict__ paths,
    const int* __restrict__ elen)
{
    const int bp = blockIdx.x;
    const int b  = bp / PP;
    const int len = elen[b];
    const int* pp = paths + (size_t)bp * TT;
    const unsigned* map = g_map + (size_t)b * VV;
    const int tid = threadIdx.x;
    const int t0 = tid * 8;

    int4 A = *(const int4*)(pp + t0);
    int4 Bv = *(const int4*)(pp + t0 + 4);
    int tok[8] = {A.x, A.y, A.z, A.w, Bv.x, Bv.y, Bv.z, Bv.w};
    const int prev0 = (t0 == 0) ? -1 : __ldg(pp + t0 - 1);

    unsigned char id[8];
    #pragma unroll
    for (int i = 0; i < 8; ++i)
        id[i] = (unsigned char)(__ldg(map + tok[i]) + 1u);   // 0 if not in label

    unsigned flags = 0;
    int cnt = 0;
    #pragma unroll
    for (int i = 0; i < 8; ++i) {
        int pr = (i == 0) ? prev0 : tok[i - 1];
        int v = ((t0 + i) < len) & (tok[i] != 0) & (tok[i] != pr);
        flags |= (unsigned)v << i;
        cnt += v;
    }

    const int lane = tid & 31, w = tid >> 5;
    int inc = cnt;
    #pragma unroll
    for (int o = 1; o < 32; o <<= 1) {
        int nn = __shfl_up_sync(0xffffffffu, inc, o);
        if (lane >= o) inc += nn;
    }
    __shared__ int wtot[4];
    if (lane == 31) wtot[w] = inc;
    __syncthreads();
    int wbase = 0;
    #pragma unroll
    for (int i = 0; i < 4; ++i) wbase += (i < w) ? wtot[i] : 0;
    int base = wbase + inc - cnt;

    unsigned char* out = g_ctok + (size_t)bp * TT;
    #pragma unroll
    for (int i = 0; i < 8; ++i)
        if ((flags >> i) & 1u) out[base++] = id[i];
    __syncthreads();
    if (tid == 0) g_clen[bp] = wtot[0] + wtot[1] + wtot[2] + wtot[3];
}

// ---------------------------------------------------------------------------
// Skew-4 Myers: lane w owns state word w and processes tokens 4(s-w)..+3 at
// wall-step s. One shfl (12 packed bits: carry/hp31/hn31 x 4 tokens) per
// 4 tokens. Score via final-state popc invariant D[n][m] = n + pop(VP) - pop(VN).
// ---------------------------------------------------------------------------
template<bool GUARD>
__device__ __forceinline__ void block16_skew4(
    const unsigned* __restrict__ peqw, int w,
    int tBase0, int n, unsigned c_and, unsigned hp_pat,
    unsigned C0, unsigned C1, unsigned C2, unsigned C3, unsigned Cn0,
    unsigned& VP, unsigned& VN, unsigned& Eq_a, unsigned& Eq_b,
    unsigned& msgOut)
{
    unsigned Cw[4] = {C0, C1, C2, C3};
    #pragma unroll
    for (int s = 0; s < 4; ++s) {
        const unsigned msgIn = __shfl_up_sync(0xffffffffu, msgOut, 1, 4);
        const unsigned mAA = (msgIn & c_and) | hp_pat;
        unsigned newMsg = 0;
        #pragma unroll
        for (int j = 0; j < 4; ++j) {
            const int k = 4 * s + j;
            const unsigned Eq = (k & 1) ? Eq_b : Eq_a;
            // prefetch PEQ word for token k+2 (depth-2 double buffer)
            const int kk = k + 2;
            const unsigned idn = (kk < 16)
                ? __byte_perm(Cw[kk >> 2], 0, 0x4440 | (kk & 3))
                : __byte_perm(Cn0, 0, 0x4440 | (kk & 3));
            const unsigned Eqn = peqw[(idn << 2) + w];
            if (k & 1) Eq_b = Eqn; else Eq_a = Eqn;

            const unsigned cin  = (mAA >> (3 * j)) & 1u;
            const unsigned hpin = (mAA >> (3 * j + 1)) & 1u;
            const unsigned hnin = (mAA >> (3 * j + 2)) & 1u;

            const unsigned a = Eq & VP;
            const unsigned long long wide = (unsigned long long)a + VP + cin;
            const unsigned sum  = (unsigned)wide;
            const unsigned cout = (unsigned)(wide >> 32);
            unsigned X; LOP3_(X, sum, VP, Eq, 0xBE);   // (sum^VP)|Eq
            const unsigned D = X | VN;
            unsigned HP; LOP3_(HP, VN, D, VP, 0xF1);   // VN | ~(D|VP)
            const unsigned HN = VP & D;

            newMsg |= (cout << (3 * j)) | ((HP >> 31) << (3 * j + 1))
                    | ((HN >> 31) << (3 * j + 2));

            const unsigned HPs = (HP << 1) | hpin;
            const unsigned HNs = (HN << 1) | hnin;
            unsigned nVP; LOP3_(nVP, HNs, D, HPs, 0xF1);
            const unsigned nVN = D & HPs;
            if (GUARD) {
                const bool act = ((unsigned)(tBase0 + k) < (unsigned)n);
                VP = act ? nVP : VP;
                VN = act ? nVN : VN;
            } else { VP = nVP; VN = nVN; }
        }
        msgOut = newMsg;
    }
}

__device__ __forceinline__ void edit_body(
    int blk, const int* __restrict__ labels, const int* __restrict__ llen,
    char* smem_raw)
{
    unsigned* peqw = (unsigned*)smem_raw;    // 256 ids * 4 words = 4KB
    const int b = blk >> 2;
    const int pbase = (blk & 3) * 32;
    const int tid = threadIdx.x;

    for (int i = tid; i < 1024; i += 128) peqw[i] = 0u;
    __syncthreads();
    const int m = llen[b];                   // 64..128, uniform per b
    if (tid < m) {
        int c = labels[b * LL + tid];
        unsigned mp = __ldg(&g_map[(size_t)b * VV + c]);
        atomicOr(&peqw[((mp + 1) << 2) + (tid >> 5)], 1u << (tid & 31));
    }
    __syncthreads();

    const int w = tid & 3;                   // state word index
    const int p_raw = pbase + (tid >> 2);    // path within b
    const int p = (p_raw < PP) ? p_raw : (PP - 1);
    const int gp = b * PP + p;
    const int n = g_clen[gp];
    const unsigned char* ct = g_ctok + (size_t)gp * TT;

    int nMax = n, nMin = n;
    #pragma unroll
    for (int o = 16; o; o >>= 1) {
        nMax = max(nMax, __shfl_xor_sync(0xffffffffu, nMax, o));
        nMin = min(nMin, __shfl_xor_sync(0xffffffffu, nMin, o));
    }

    // word mask for bits of the pattern this lane owns (m >= 64 always)
    unsigned mask;
    if (w < 2)       mask = ~0u;
    else if (w == 2) mask = (m >= 96)  ? ~0u : ((m > 64) ? ((1u << (m - 64)) - 1u) : 0u);
    else             mask = (m >= 128) ? ~0u : ((m > 96) ? ((1u << (m - 96)) - 1u) : 0u);
    unsigned VP = mask, VN = 0u;

    const unsigned c_and  = w ? ~0u : 0u;
    const unsigned hp_pat = w ? 0u : 0x492u;   // hp=1 boundary bits (pos 1,4,7,10)
    unsigned msgOut = 0u;

    uint4 P  = make_uint4(0, 0, 0, 0);         // V_{-4..-1} (garbage-safe)
    uint4 B  = *(const uint4*)(ct);            // V_{0..3}
    uint4 Bn = *(const uint4*)(ct + 16);

    // prime window + Eq double-buffer for J=0
    unsigned C0 = (w == 0) ? B.x : ((w == 1) ? P.w : ((w == 2) ? P.z : P.y));
    unsigned C1 = (w == 0) ? B.y : ((w == 1) ? B.x : ((w == 2) ? P.w : P.z));
    unsigned C2 = (w == 0) ? B.z : ((w == 1) ? B.y : ((w == 2) ? B.x : P.w));
    unsigned C3 = (w == 0) ? B.w : ((w == 1) ? B.z : ((w == 2) ? B.y : B.x));
    unsigned Eq_a = peqw[((C0 & 0xFFu) << 2) + w];
    unsigned Eq_b = peqw[(((C0 >> 8) & 0xFFu) << 2) + w];

    const int Jend = nMax + 12;                // run blocks J < Jend (step 16)
    for (int J = 0; J < Jend; J += 16) {
        const uint4 Bf = *(const uint4*)(ct + J + 32);   // <= TT+128 pad: safe
        // next block's window word 0 (for tail Eq prefetch)
        const unsigned Cn0 = (w == 0) ? Bn.x : ((w == 1) ? B.w
                           : ((w == 2) ? B.z : B.y));

        if (J >= 16 && (J + 16) <= nMin) {
            block16_skew4<false>(peqw, w, J - 4 * w, n, c_and, hp_pat,
                                 C0, C1, C2, C3, Cn0,
                                 VP, VN, Eq_a, Eq_b, msgOut);
        } else {
            block16_skew4<true>(peqw, w, J - 4 * w, n, c_and, hp_pat,
                                C0, C1, C2, C3, Cn0,
                                VP, VN, Eq_a, Eq_b, msgOut);
        }

        // advance stream and rebuild window
        P = B; B = Bn; Bn = Bf;
        C0 = (w == 0) ? B.x : ((w == 1) ? P.w : ((w == 2) ? P.z : P.y));
        C1 = (w == 0) ? B.y : ((w == 1) ? B.x : ((w == 2) ? P.w : P.z));
        C2 = (w == 0) ? B.z : ((w == 1) ? B.y : ((w == 2) ? B.x : P.w));
        C3 = (w == 0) ? B.w : ((w == 1) ? B.z : ((w == 2) ? B.y : B.x));
    }

    // D[n][m] = n + popc(VP&mask) - popc(VN&mask), summed over the 4 words
    int partial = __popc(VP & mask) - __popc(VN & mask);
    partial += __shfl_xor_sync(0xffffffffu, partial, 1, 4);
    partial += __shfl_xor_sync(0xffffffffu, partial, 2, 4);
    if ((tid & 3) == 0 && p_raw < PP)
        g_wers[b * PP + p_raw] = (float)(n + partial);
    __syncthreads();
}

// ---------------------------------------------------------------------------
// Scores: log-softmax normalizer cancels in the per-b softmax over paths.
// ---------------------------------------------------------------------------
__device__ __forceinline__ void scores_body(
    int bp, const float* __restrict__ em, const int* __restrict__ elen,
    const int* __restrict__ paths, char* smem_raw)
{
    const int b   = bp / PP;
    const int len = elen[b];
    const int* pp = paths + (size_t)bp * TT;
    const float* eb = em + (size_t)b * TT * VV;
    const int tid = threadIdx.x;
    const int t0 = tid * 8;

    int4 A = *(const int4*)(pp + t0);
    int4 Bv = *(const int4*)(pp + t0 + 4);
    int tok[8] = {A.x, A.y, A.z, A.w, Bv.x, Bv.y, Bv.z, Bv.w};

    float a0 = 0.f, a1 = 0.f, a2 = 0.f, a3 = 0.f;
    #pragma unroll
    for (int i = 0; i < 8; i += 4) {
        if (t0 + i + 0 < len) a0 += __ldg(eb + (size_t)(t0 + i + 0) * VV + tok[i + 0]);
        if (t0 + i + 1 < len) a1 += __ldg(eb + (size_t)(t0 + i + 1) * VV + tok[i + 1]);
        if (t0 + i + 2 < len) a2 += __ldg(eb + (size_t)(t0 + i + 2) * VV + tok[i + 2]);
        if (t0 + i + 3 < len) a3 += __ldg(eb + (size_t)(t0 + i + 3) * VV + tok[i + 3]);
    }
    float acc = (a0 + a1) + (a2 + a3);
    #pragma unroll
    for (int o = 16; o; o >>= 1) acc += __shfl_down_sync(0xffffffffu, acc, o);
    float* ws = (float*)smem_raw;
    if ((tid & 31) == 0) ws[tid >> 5] = acc;
    __syncthreads();
    if (tid == 0) g_scores[bp] = ws[0] + ws[1] + ws[2] + ws[3];
    __syncthreads();
}

__device__ __forceinline__ void finalize_body(float* out, char* smem_raw)
{
    float* red = (float*)smem_raw;
    const int tid = threadIdx.x;
    float total = 0.f;
    __threadfence();

    for (int b = 0; b < BB; ++b) {
        float s = (tid < PP) ? g_scores[b * PP + tid] : -3.0e38f;
        red[tid] = s; __syncthreads();
        #pragma unroll
        for (int o = 64; o; o >>= 1) {
            if (tid < o) red[tid] = fmaxf(red[tid], red[tid + o]);
            __syncthreads();
        }
        const float mx = red[0];
        __syncthreads();

        const float e  = (tid < PP) ? expf(s - mx) : 0.f;
        const float ew = (tid < PP) ? e * g_wers[b * PP + tid] : 0.f;

        red[tid] = e; __syncthreads();
        #pragma unroll
        for (int o = 64; o; o >>= 1) {
            if (tid < o) red[tid] += red[tid + o];
            __syncthreads();
        }
        const float Z = red[0];
        __syncthreads();

        red[tid] = ew; __syncthreads();
        #pragma unroll
        for (int o = 64; o; o >>= 1) {
            if (tid < o) red[tid] += red[tid + o];
            __syncthreads();
        }
        const float S = red[0];
        __syncthreads();

        total += S / Z;
    }
    if (tid == 0) out[0] = total;
}

__global__ void __launch_bounds__(128) fused_kernel(
    const float* __restrict__ em,
    const int* __restrict__ elen,
    const int* __restrict__ paths,
    const int* __restrict__ labels,
    const int* __restrict__ llen,
    float* __restrict__ out)
{
    extern __shared__ char smem_raw[];
    __shared__ unsigned s_rank;

    if (blockIdx.x < NEDIT)
        edit_body(blockIdx.x, labels, llen, smem_raw);
    else
        scores_body(blockIdx.x - NEDIT, em, elen, paths, smem_raw);

    if (threadIdx.x == 0) {
        __threadfence();
        s_rank = atomicAdd(&g_done, 1u);
    }
    __syncthreads();
    if (s_rank == (unsigned)(NEDIT + BB * PP - 1))
        finalize_body(out, smem_raw);
}

// ---------------------------------------------------------------------------
extern "C" void kernel_launch(void* const* d_in, const int* in_sizes, int n_in,
                              void* d_out, int out_size)
{
    const float* em     = (const float*)d_in[0];  // (B,T,V) f32
    const int*   elen   = (const int*)  d_in[1];  // (B,)
    const int*   labels = (const int*)  d_in[2];  // (B,L)
    const int*   llen   = (const int*)  d_in[3];  // (B,)
    const int*   paths  = (const int*)  d_in[4];  // (B,P,T)

    clear_kernel<<<256, 128>>>();
    scatter_kernel<<<BB, 128>>>(labels, llen);
    compact_kernel<<<BB * PP, 128>>>(paths, elen);

    const int smem = 4096 + 512;   // peq (4KB) + reduction scratch
    fused_kernel<<<NEDIT + BB * PP, 128, smem>>>(em, elen, paths, labels, llen,
                                                 (float*)d_out);
}

// round 15
// speedup vs baseline: 1.1991x; 1.1991x over previous
#include <cuda_runtime.h>
#include <cuda_bf16.h>
#include <math.h>

#define BB 16
#define TT 1024
#define VV 4096
#define PP 100
#define LL 128
#define NEDIT 64          // 4 blocks per b, 32 paths per block (4 lanes/path)
#define NSCORE 200        // fat scores blocks, 8 bp each

// scratch (allocation-free rule: __device__ globals)
__device__ unsigned g_map[BB * VV];                       // per-b vocab -> minpos
__device__ unsigned char g_ctok[BB * PP * TT + 128];      // compacted token ids (u8)
__device__ int g_clen[BB * PP];
__device__ float g_scores[BB * PP];
__device__ float g_wers[BB * PP];
__device__ unsigned g_done;

// forced 3-input LOP3 with explicit immLut
#define LOP3_(r, a, b, c, imm)                                          \
    asm("lop3.b32 %0, %1, %2, %3, %4;"                                  \
        : "=r"(r) : "r"(a), "r"(b), "r"(c), "n"(imm))

// ---------------------------------------------------------------------------
// Kernel A1: wide clear of the vocab map (+ done counter).
// ---------------------------------------------------------------------------
__global__ void __launch_bounds__(128) clear_kernel()
{
    const unsigned idx = blockIdx.x * 128u + threadIdx.x;
    uint4* mp = (uint4*)g_map;
    const uint4 f = make_uint4(~0u, ~0u, ~0u, ~0u);
    for (unsigned i = idx; i < (BB * VV) / 4; i += gridDim.x * 128u) mp[i] = f;
    if (idx == 0) g_done = 0;
}

// ---------------------------------------------------------------------------
// Kernel A2: map[b][c] = min label position of char c. id(c) = map[c]+1
// (wraps to 0 for chars not in the label).
// ---------------------------------------------------------------------------
__global__ void __launch_bounds__(128) scatter_kernel(
    const int* __restrict__ labels,
    const int* __restrict__ llen)
{
    const int b = blockIdx.x, tid = threadIdx.x;
    if (tid < llen[b])
        atomicMin(&g_map[(size_t)b * VV + labels[b * LL + tid]], (unsigned)tid);
}

// ---------------------------------------------------------------------------
// Kernel B: CTC-collapse + remap to u8 ids. One block per (b,p).
// valid = tok!=0 && tok!=raw_prev && t<len.
// ---------------------------------------------------------------------------
__global__ void __launch_bounds__(128) compact_kernel(
    const int* __restrict__ paths,
    const int* __restrict__ elen)
{
    const int bp = blockIdx.x;
    const int b  = bp / PP;
    const int len = elen[b];
    const int* pp = paths + (size_t)bp * TT;
    const unsigned* map = g_map + (size_t)b * VV;
    const int tid = threadIdx.x;
    const int t0 = tid * 8;

    int4 A = *(const int4*)(pp + t0);
    int4 Bv = *(const int4*)(pp + t0 + 4);
    int tok[8] = {A.x, A.y, A.z, A.w, Bv.x, Bv.y, Bv.z, Bv.w};
    const int prev0 = (t0 == 0) ? -1 : __ldg(pp + t0 - 1);

    unsigned char id[8];
    #pragma unroll
    for (int i = 0; i < 8; ++i)
        id[i] = (unsigned char)(__ldg(map + tok[i]) + 1u);   // 0 if not in label

    unsigned flags = 0;
    int cnt = 0;
    #pragma unroll
    for (int i = 0; i < 8; ++i) {
        int pr = (i == 0) ? prev0 : tok[i - 1];
        int v = ((t0 + i) < len) & (tok[i] != 0) & (tok[i] != pr);
        flags |= (unsigned)v << i;
        cnt += v;
    }

    const int lane = tid & 31, w = tid >> 5;
    int inc = cnt;
    #pragma unroll
    for (int o = 1; o < 32; o <<= 1) {
        int nn = __shfl_up_sync(0xffffffffu, inc, o);
        if (lane >= o) inc += nn;
    }
    __shared__ int wtot[4];
    if (lane == 31) wtot[w] = inc;
    __syncthreads();
    int wbase = 0;
    #pragma unroll
    for (int i = 0; i < 4; ++i) wbase += (i < w) ? wtot[i] : 0;
    int base = wbase + inc - cnt;

    unsigned char* out = g_ctok + (size_t)bp * TT;
    #pragma unroll
    for (int i = 0; i < 8; ++i)
        if ((flags >> i) & 1u) out[base++] = id[i];
    __syncthreads();
    if (tid == 0) g_clen[bp] = wtot[0] + wtot[1] + wtot[2] + wtot[3];
}

// ---------------------------------------------------------------------------
// Skewed Myers (R13 verbatim): 4 lanes per path, lane w owns state word w,
// processes token t = wall_step - w. One packed shfl per step.
// ---------------------------------------------------------------------------
__device__ __forceinline__ void build_win(
    int w, unsigned sh, unsigned Pl, uint4 B,
    unsigned& C0, unsigned& C1, unsigned& C2, unsigned& C3)
{
    if (w == 0) { C0 = B.x; C1 = B.y; C2 = B.z; C3 = B.w; }
    else {
        C0 = __funnelshift_r(Pl,  B.x, sh);
        C1 = __funnelshift_r(B.x, B.y, sh);
        C2 = __funnelshift_r(B.y, B.z, sh);
        C3 = __funnelshift_r(B.z, B.w, sh);
    }
}

template<bool GUARD>
__device__ __forceinline__ void edit_block16(
    const unsigned* __restrict__ peqw, int w, int base_t,
    int n, bool isSel, int mbit,
    unsigned C0, unsigned C1, unsigned C2, unsigned C3, unsigned Cn0,
    unsigned& VP, unsigned& VN, unsigned& Eq_a, unsigned& Eq_b,
    unsigned& msgOut, int& score,
    unsigned c_and, unsigned hp_or)
{
    unsigned Cw[4] = {C0, C1, C2, C3};
    #pragma unroll
    for (int i = 0; i < 16; ++i) {
        const unsigned Eq = (i & 1) ? Eq_b : Eq_a;
        // prefetch PEQ word for step i+2 (depth-2)
        const int k = i + 2;
        const unsigned idn = (k < 16)
            ? __byte_perm(Cw[k >> 2], 0, 0x4440 | (k & 3))
            : __byte_perm(Cn0, 0, 0x4440 | (k & 3));
        const unsigned Eqn = peqw[(idn << 2) + w];
        if (i & 1) Eq_b = Eqn; else Eq_a = Eqn;

        // message from lane w-1 (produced at previous wall-step, same token)
        const unsigned msgIn = __shfl_up_sync(0xffffffffu, msgOut, 1, 4);
        const unsigned cin  = msgIn & c_and;
        const unsigned hpin = ((msgIn >> 1) & c_and) | hp_or;
        const unsigned hnin = (msgIn >> 2) & c_and;

        const unsigned a = Eq & VP;
        const unsigned long long wide = (unsigned long long)a + VP + cin;
        const unsigned sum  = (unsigned)wide;
        const unsigned cout = (unsigned)(wide >> 32);
        unsigned X; LOP3_(X, sum, VP, Eq, 0xBE);   // (sum^VP)|Eq
        const unsigned D = X | VN;
        unsigned HP; LOP3_(HP, VN, D, VP, 0xF1);   // VN | ~(D|VP)
        const unsigned HN = VP & D;

        const int t = base_t + i;
        const int d = (int)((HP >> mbit) & 1u) - (int)((HN >> mbit) & 1u);
        score += (isSel & ((unsigned)t < (unsigned)n)) ? d : 0;

        msgOut = cout | (((HP >> 31) & 1u) << 1) | ((HN >> 31) << 2);

        const unsigned HPs = (HP << 1) | hpin;
        const unsigned HNs = (HN << 1) | hnin;
        unsigned nVP; LOP3_(nVP, HNs, D, HPs, 0xF1);
        const unsigned nVN = D & HPs;
        if (GUARD) {
            const bool act = (t >= 0);
            VP = act ? nVP : VP;
            VN = act ? nVN : VN;
        } else {
            VP = nVP; VN = nVN;
        }
    }
}

__device__ __forceinline__ void edit_body(
    int blk, const int* __restrict__ labels, const int* __restrict__ llen,
    char* smem_raw)
{
    unsigned* peqw = (unsigned*)smem_raw;    // 256 ids * 4 words = 4KB
    const int b = blk >> 2;
    const int pbase = (blk & 3) * 32;
    const int tid = threadIdx.x;

    for (int i = tid; i < 1024; i += 128) peqw[i] = 0u;
    __syncthreads();
    const int m = llen[b];                   // 64..128, uniform per b
    if (tid < m) {
        int c = labels[b * LL + tid];
        unsigned mp = __ldg(&g_map[(size_t)b * VV + c]);
        atomicOr(&peqw[((mp + 1) << 2) + (tid >> 5)], 1u << (tid & 31));
    }
    __syncthreads();

    const int w = tid & 3;                   // word index
    const int p_raw = pbase + (tid >> 2);    // path within b
    const int p = (p_raw < PP) ? p_raw : (PP - 1);
    const int gp = b * PP + p;
    const int n = g_clen[gp];
    const unsigned char* ct = g_ctok + (size_t)gp * TT;

    int nW = n;
    #pragma unroll
    for (int o = 16; o; o >>= 1) nW = max(nW, __shfl_xor_sync(0xffffffffu, nW, o));
    const int nWall = ((nW + 3) + 15) & ~15;

    unsigned VP;
    if (w < 2)      VP = ~0u;
    else if (w == 2) VP = (m >= 96)  ? ~0u : ((m > 64) ? ((1u << (m - 64)) - 1u) : 0u);
    else             VP = (m >= 128) ? ~0u : ((m > 96) ? ((1u << (m - 96)) - 1u) : 0u);
    unsigned VN = 0u;

    const int wsel = (m - 1) >> 5, mbit = (m - 1) & 31;
    const bool isSel = (w == wsel);
    const unsigned c_and = w ? 1u : 0u;
    const unsigned hp_or = w ? 0u : 1u;
    const unsigned sh = (unsigned)(32 - 8 * w);

    int score = 0;
    unsigned msgOut = 0;

    uint4 B  = *(const uint4*)(ct);
    uint4 Bn = *(const uint4*)(ct + 16);
    unsigned C0, C1, C2, C3;
    build_win(w, sh, 0u, B, C0, C1, C2, C3);
    unsigned Eq_a = peqw[(__byte_perm(C0, 0, 0x4440) << 2) + w];
    unsigned Eq_b = peqw[(__byte_perm(C0, 0, 0x4441) << 2) + w];

    // peeled first wall-block (lead-in guard: lanes w>0 idle for t<0)
    {
        uint4 Bf = *(const uint4*)(ct + 32);
        unsigned Cn0, Cn1, Cn2, Cn3;
        build_win(w, sh, B.w, Bn, Cn0, Cn1, Cn2, Cn3);
        edit_block16<true>(peqw, w, 0 - w, n, isSel, mbit,
                           C0, C1, C2, C3, Cn0,
                           VP, VN, Eq_a, Eq_b, msgOut, score, c_and, hp_or);
        C0 = Cn0; C1 = Cn1; C2 = Cn2; C3 = Cn3;
        B = Bn; Bn = Bf;
    }
    for (int J = 16; J < nWall; J += 16) {
        uint4 Bf = *(const uint4*)(ct + J + 32);   // within +128 global pad
        unsigned Cn0, Cn1, Cn2, Cn3;
        build_win(w, sh, B.w, Bn, Cn0, Cn1, Cn2, Cn3);
        edit_block16<false>(peqw, w, J - w, n, isSel, mbit,
                            C0, C1, C2, C3, Cn0,
                            VP, VN, Eq_a, Eq_b, msgOut, score, c_and, hp_or);
        C0 = Cn0; C1 = Cn1; C2 = Cn2; C3 = Cn3;
        B = Bn; Bn = Bf;
    }

    if (isSel && p_raw < PP)
        g_wers[b * PP + p_raw] = (float)(m + score);
    __syncthreads();
}

// ---------------------------------------------------------------------------
// Scores: log-softmax normalizer cancels in the per-b softmax over paths.
// Fat blocks: each handles 8 consecutive bp (6x fewer warps on chip ->
// edit blocks get issue slots from t=0 instead of starving behind the flood).
// ---------------------------------------------------------------------------
__device__ __forceinline__ void scores_multi(
    int blk, const float* __restrict__ em, const int* __restrict__ elen,
    const int* __restrict__ paths, char* smem_raw)
{
    const int tid = threadIdx.x;
    const int t0 = tid * 8;
    float* ws = (float*)smem_raw;

    #pragma unroll 1
    for (int q = 0; q < 8; ++q) {
        const int bp  = blk * 8 + q;
        const int b   = bp / PP;
        const int len = elen[b];
        const int* pp = paths + (size_t)bp * TT;
        const float* eb = em + (size_t)b * TT * VV;

        int4 A = *(const int4*)(pp + t0);
        int4 Bv = *(const int4*)(pp + t0 + 4);
        int tok[8] = {A.x, A.y, A.z, A.w, Bv.x, Bv.y, Bv.z, Bv.w};

        float a0 = 0.f, a1 = 0.f, a2 = 0.f, a3 = 0.f;
        #pragma unroll
        for (int i = 0; i < 8; i += 4) {
            if (t0 + i + 0 < len) a0 += __ldg(eb + (size_t)(t0 + i + 0) * VV + tok[i + 0]);
            if (t0 + i + 1 < len) a1 += __ldg(eb + (size_t)(t0 + i + 1) * VV + tok[i + 1]);
            if (t0 + i + 2 < len) a2 += __ldg(eb + (size_t)(t0 + i + 2) * VV + tok[i + 2]);
            if (t0 + i + 3 < len) a3 += __ldg(eb + (size_t)(t0 + i + 3) * VV + tok[i + 3]);
        }
        float acc = (a0 + a1) + (a2 + a3);
        #pragma unroll
        for (int o = 16; o; o >>= 1) acc += __shfl_down_sync(0xffffffffu, acc, o);
        if ((tid & 31) == 0) ws[tid >> 5] = acc;
        __syncthreads();
        if (tid == 0) g_scores[bp] = ws[0] + ws[1] + ws[2] + ws[3];
        __syncthreads();
    }
}

__device__ __forceinline__ void finalize_body(float* out, char* smem_raw)
{
    float* red = (float*)smem_raw;
    const int tid = threadIdx.x;
    float total = 0.f;
    __threadfence();

    for (int b = 0; b < BB; ++b) {
        float s = (tid < PP) ? g_scores[b * PP + tid] : -3.0e38f;
        red[tid] = s; __syncthreads();
        #pragma unroll
        for (int o = 64; o; o >>= 1) {
            if (tid < o) red[tid] = fmaxf(red[tid], red[tid + o]);
            __syncthreads();
        }
        const float mx = red[0];
        __syncthreads();

        const float e  = (tid < PP) ? expf(s - mx) : 0.f;
        const float ew = (tid < PP) ? e * g_wers[b * PP + tid] : 0.f;

        red[tid] = e; __syncthreads();
        #pragma unroll
        for (int o = 64; o; o >>= 1) {
            if (tid < o) red[tid] += red[tid + o];
            __syncthreads();
        }
        const float Z = red[0];
        __syncthreads();

        red[tid] = ew; __syncthreads();
        #pragma unroll
        for (int o = 64; o; o >>= 1) {
            if (tid < o) red[tid] += red[tid + o];
            __syncthreads();
        }
        const float S = red[0];
        __syncthreads();

        total += S / Z;
    }
    if (tid == 0) out[0] = total;
}

__global__ void __launch_bounds__(128) fused_kernel(
    const float* __restrict__ em,
    const int* __restrict__ elen,
    const int* __restrict__ paths,
    const int* __restrict__ labels,
    const int* __restrict__ llen,
    float* __restrict__ out)
{
    extern __shared__ char smem_raw[];
    __shared__ unsigned s_rank;

    if (blockIdx.x < NEDIT)
        edit_body(blockIdx.x, labels, llen, smem_raw);
    else
        scores_multi(blockIdx.x - NEDIT, em, elen, paths, smem_raw);

    if (threadIdx.x == 0) {
        __threadfence();
        s_rank = atomicAdd(&g_done, 1u);
    }
    __syncthreads();
    if (s_rank == (unsigned)(NEDIT + NSCORE - 1))
        finalize_body(out, smem_raw);
}

// ---------------------------------------------------------------------------
extern "C" void kernel_launch(void* const* d_in, const int* in_sizes, int n_in,
                              void* d_out, int out_size)
{
    const float* em     = (const float*)d_in[0];  // (B,T,V) f32
    const int*   elen   = (const int*)  d_in[1];  // (B,)
    const int*   labels = (const int*)  d_in[2];  // (B,L)
    const int*   llen   = (const int*)  d_in[3];  // (B,)
    const int*   paths  = (const int*)  d_in[4];  // (B,P,T)

    clear_kernel<<<256, 128>>>();
    scatter_kernel<<<BB, 128>>>(labels, llen);
    compact_kernel<<<BB * PP, 128>>>(paths, elen);

    const int smem = 4096 + 512;   // peq (4KB) + reduction scratch
    fused_kernel<<<NEDIT + NSCORE, 128, smem>>>(em, elen, paths, labels, llen,
                                                (float*)d_out);
}